// round 3
// baseline (speedup 1.0000x reference)
#include <cuda_runtime.h>
#include <cstdint>

// GRU_12962211299468 : B=65536, T=9, I=57, H=2, O=1, fp32
// Persistent double-buffered TMA-bulk pipeline.
//   tile = 8 batch elements = 72 (b,t) rows = 16416 contiguous bytes of x
//   producer: cp.async.bulk (UBLKCP) gmem->smem, mbarrier complete_tx
//   projection: 72 threads, one row each (6x57 dot from smem)
//   recurrence: 8 lanes of warp 2, 9-step GRU + FC from double-buffered sgx
// One __syncthreads per tile; TMA for tile k+1 in flight during compute of k.

#define T_STEPS 9
#define I_DIM   57
#define NB_TILE 8
#define ROWS    (NB_TILE * T_STEPS)        // 72
#define TILE_FLOATS (ROWS * I_DIM)         // 4104
#define TILE_BYTES  (TILE_FLOATS * 4)      // 16416
#define NTHR    96
#define WROW    60
#define N_TILES 8192                       // 65536 / NB_TILE
#define GRID    740

__device__ __forceinline__ uint32_t s2u(const void* p) {
    uint32_t a;
    asm("{ .reg .u64 t; cvta.to.shared.u64 t, %1; cvt.u32.u64 %0, t; }"
        : "=r"(a) : "l"(p));
    return a;
}

__device__ __forceinline__ void mbar_init(uint32_t addr, uint32_t cnt) {
    asm volatile("mbarrier.init.shared.b64 [%0], %1;" :: "r"(addr), "r"(cnt) : "memory");
}
__device__ __forceinline__ void mbar_expect_tx(uint32_t addr, uint32_t bytes) {
    asm volatile("mbarrier.arrive.expect_tx.shared.b64 _, [%0], %1;"
                 :: "r"(addr), "r"(bytes) : "memory");
}
__device__ __forceinline__ void mbar_wait(uint32_t addr, uint32_t phase) {
    asm volatile(
        "{\n\t"
        ".reg .pred P;\n\t"
        "WL%=:\n\t"
        "mbarrier.try_wait.parity.acquire.cta.shared::cta.b64 P, [%0], %1, 0x989680;\n\t"
        "@!P bra WL%=;\n\t"
        "}"
        :: "r"(addr), "r"(phase) : "memory");
}
__device__ __forceinline__ void tma_bulk(uint32_t dst_smem, const void* src,
                                         uint32_t bytes, uint32_t mbar_addr) {
    asm volatile(
        "cp.async.bulk.shared::cta.global.mbarrier::complete_tx::bytes [%0], [%1], %2, [%3];"
        :: "r"(dst_smem), "l"(src), "r"(bytes), "r"(mbar_addr) : "memory");
}

__device__ __forceinline__ float sigf(float v) {
    return 1.0f / (1.0f + __expf(-v));
}
__device__ __forceinline__ float tanh_ex(float v) {
    return 1.0f - 2.0f / (__expf(2.0f * v) + 1.0f);
}

__global__ __launch_bounds__(NTHR) void gru_pipe(
    const float* __restrict__ x,
    const float* __restrict__ Wih,   // [6,57]
    const float* __restrict__ Whh,   // [6,2]
    const float* __restrict__ bih,   // [6]
    const float* __restrict__ bhh,   // [6]
    const float* __restrict__ fcw,   // [2]
    const float* __restrict__ fcb,   // [1]
    float* __restrict__ out)         // [B]
{
    __shared__ __align__(128) float bufA[TILE_FLOATS];
    __shared__ __align__(128) float bufB[TILE_FLOATS];
    __shared__ float sw[6 * WROW];
    __shared__ float sgx[2][ROWS * 6];
    __shared__ __align__(8) unsigned long long mbar_store[2];

    const int tid = threadIdx.x;
    const uint32_t mb0 = s2u(&mbar_store[0]);
    const uint32_t mb1 = mb0 + 8;
    const uint32_t sbufA = s2u(bufA);
    const uint32_t sbufB = s2u(bufB);

    // ---- stage W_ih (padded rows), init mbarriers ----
    for (int j = tid; j < 6 * WROW; j += NTHR) {
        int g = j / WROW;
        int i = j - g * WROW;
        sw[j] = (i < I_DIM) ? Wih[g * I_DIM + i] : 0.0f;
    }
    if (tid == 0) {
        mbar_init(mb0, 1);
        mbar_init(mb1, 1);
        asm volatile("fence.proxy.async.shared::cta;" ::: "memory");
    }

    // per-thread hoisted constants
    float bi0 = bih[0], bi1 = bih[1], bi2 = bih[2];
    float bi3 = bih[3], bi4 = bih[4], bi5 = bih[5];

    float w00 = 0.f, w01 = 0.f, w10 = 0.f, w11 = 0.f, w20 = 0.f, w21 = 0.f;
    float w30 = 0.f, w31 = 0.f, w40 = 0.f, w41 = 0.f, w50 = 0.f, w51 = 0.f;
    float bh0 = 0.f, bh1 = 0.f, bh2 = 0.f, bh3 = 0.f, bh4 = 0.f, bh5 = 0.f;
    float fw0 = 0.f, fw1 = 0.f, fb = 0.f;
    if (tid >= 88) {
        w00 = Whh[0];  w01 = Whh[1];
        w10 = Whh[2];  w11 = Whh[3];
        w20 = Whh[4];  w21 = Whh[5];
        w30 = Whh[6];  w31 = Whh[7];
        w40 = Whh[8];  w41 = Whh[9];
        w50 = Whh[10]; w51 = Whh[11];
        bh0 = bhh[0]; bh1 = bhh[1]; bh2 = bhh[2];
        bh3 = bhh[3]; bh4 = bhh[4]; bh5 = bhh[5];
        fw0 = fcw[0]; fw1 = fcw[1]; fb = fcb[0];
    }

    __syncthreads();   // mbarriers + sw visible

    // ---- prologue: kick TMA for first tile ----
    int tile = blockIdx.x;
    if (tid == 0) {
        mbar_expect_tx(mb0, TILE_BYTES);
        tma_bulk(sbufA, x + (size_t)tile * TILE_FLOATS, TILE_BYTES, mb0);
    }

    uint32_t ph0 = 0, ph1 = 0;
    int buf = 0;

    while (tile < N_TILES) {
        const int next = tile + GRID;

        // prefetch next tile into the other buffer (safe: its last consumer
        // finished before the __syncthreads of the previous iteration)
        if (next < N_TILES && tid == 0) {
            uint32_t mb = buf ? mb0 : mb1;
            uint32_t sb = buf ? sbufA : sbufB;
            mbar_expect_tx(mb, TILE_BYTES);
            tma_bulk(sb, x + (size_t)next * TILE_FLOATS, TILE_BYTES, mb);
        }

        // wait for current tile
        if (buf == 0) { mbar_wait(mb0, ph0); ph0 ^= 1; }
        else          { mbar_wait(mb1, ph1); ph1 ^= 1; }

        const float* bx = buf ? bufB : bufA;

        // ---- projection: one (b,t) row per thread ----
        if (tid < ROWS) {
            const float* row = bx + tid * I_DIM;   // stride-57: bank-conflict-free
            float g0 = bi0, g1 = bi1, g2 = bi2, g3 = bi3, g4 = bi4, g5 = bi5;
#pragma unroll
            for (int c = 0; c < 14; ++c) {
                float x0 = row[4 * c + 0];
                float x1 = row[4 * c + 1];
                float x2 = row[4 * c + 2];
                float x3 = row[4 * c + 3];
                float4 v;
                v = *reinterpret_cast<const float4*>(&sw[0 * WROW + 4 * c]);
                g0 += v.x * x0 + v.y * x1 + v.z * x2 + v.w * x3;
                v = *reinterpret_cast<const float4*>(&sw[1 * WROW + 4 * c]);
                g1 += v.x * x0 + v.y * x1 + v.z * x2 + v.w * x3;
                v = *reinterpret_cast<const float4*>(&sw[2 * WROW + 4 * c]);
                g2 += v.x * x0 + v.y * x1 + v.z * x2 + v.w * x3;
                v = *reinterpret_cast<const float4*>(&sw[3 * WROW + 4 * c]);
                g3 += v.x * x0 + v.y * x1 + v.z * x2 + v.w * x3;
                v = *reinterpret_cast<const float4*>(&sw[4 * WROW + 4 * c]);
                g4 += v.x * x0 + v.y * x1 + v.z * x2 + v.w * x3;
                v = *reinterpret_cast<const float4*>(&sw[5 * WROW + 4 * c]);
                g5 += v.x * x0 + v.y * x1 + v.z * x2 + v.w * x3;
            }
            {
                float xs = row[56];
                g0 += sw[0 * WROW + 56] * xs;
                g1 += sw[1 * WROW + 56] * xs;
                g2 += sw[2 * WROW + 56] * xs;
                g3 += sw[3 * WROW + 56] * xs;
                g4 += sw[4 * WROW + 56] * xs;
                g5 += sw[5 * WROW + 56] * xs;
            }
            float* gq = &sgx[buf][tid * 6];
            gq[0] = g0; gq[1] = g1; gq[2] = g2;
            gq[3] = g3; gq[4] = g4; gq[5] = g5;
        }
        __syncthreads();

        // ---- recurrence + FC: 8 lanes of warp 2 ----
        if (tid >= 88) {
            const int j = tid - 88;
            const float* gp = &sgx[buf][j * (T_STEPS * 6)];
            float h0 = 0.0f, h1 = 0.0f;
#pragma unroll
            for (int t = 0; t < T_STEPS; ++t) {
                float q0 = gp[6 * t + 0];
                float q1 = gp[6 * t + 1];
                float q2 = gp[6 * t + 2];
                float q3 = gp[6 * t + 3];
                float q4 = gp[6 * t + 4];
                float q5 = gp[6 * t + 5];

                float a0 = w00 * h0 + w01 * h1 + bh0;
                float a1 = w10 * h0 + w11 * h1 + bh1;
                float a2 = w20 * h0 + w21 * h1 + bh2;
                float a3 = w30 * h0 + w31 * h1 + bh3;
                float a4 = w40 * h0 + w41 * h1 + bh4;
                float a5 = w50 * h0 + w51 * h1 + bh5;

                float r0 = sigf(q0 + a0);
                float r1 = sigf(q1 + a1);
                float z0 = sigf(q2 + a2);
                float z1 = sigf(q3 + a3);
                float n0 = tanh_ex(q4 + r0 * a4);
                float n1 = tanh_ex(q5 + r1 * a5);

                h0 = (1.0f - z0) * n0 + z0 * h0;
                h1 = (1.0f - z1) * n1 + z1 * h1;
            }
            out[tile * NB_TILE + j] = fw0 * h0 + fw1 * h1 + fb;
        }

        buf ^= 1;
        tile = next;
    }
}

extern "C" void kernel_launch(void* const* d_in, const int* in_sizes, int n_in,
                              void* d_out, int out_size) {
    const float* x   = (const float*)d_in[0];
    const float* Wih = (const float*)d_in[1];
    const float* Whh = (const float*)d_in[2];
    const float* bih = (const float*)d_in[3];
    const float* bhh = (const float*)d_in[4];
    const float* fcw = (const float*)d_in[5];
    const float* fcb = (const float*)d_in[6];
    float* out = (float*)d_out;

    (void)in_sizes; (void)n_in; (void)out_size;

    gru_pipe<<<GRID, NTHR>>>(x, Wih, Whh, bih, bhh, fcw, fcb, out);
}